// round 14
// baseline (speedup 1.0000x reference)
#include <cuda_runtime.h>
#include <math.h>
#include <stdint.h>

#define B_   32
#define T_   128
#define D_   768
#define A_   512
#define R_   128
#define L_   50
#define NP   1280
#define BT   (B_ * T_)
#define TT   (T_ * T_)
#define EN_ELEMS (B_ * L_ * TT)
#define NLEN 128
#define MAXF 128
#define OFF_HARC 0
#define OFF_DARC 512
#define OFF_HLAB 1024
#define OFF_DLAB 1152

// ---------------------------------------------------------------------------
// Scratch (device globals; allocation is forbidden)
// ---------------------------------------------------------------------------
__device__ float g_Wt[NP * D_];
__device__ float g_bp[NP];
__device__ float g_Uat[A_ * A_];
__device__ float g_Ult[L_ * R_ * R_];
__device__ float g_proj[BT * NP];
__device__ float g_marc[BT * A_];
__device__ float g_hl[EN_ELEMS];
__device__ float g_arc[B_ * TT];
__device__ float g_narc[B_ * TT];
__device__ float g_score[B_ * TT];
__device__ int   g_labelid[B_ * TT];
__device__ unsigned char g_stk_par[B_ * MAXF * NLEN];
__device__ unsigned char g_stk_cyc[B_ * MAXF * NLEN];
__device__ int g_stk_clen[B_ * MAXF];
__device__ unsigned long long g_stk_cons[B_ * MAXF * NLEN * 2];

// ---------------------------------------------------------------------------
// helpers
// ---------------------------------------------------------------------------
__device__ __forceinline__ uint32_t f2tf32(float v) {
    uint32_t r;
    asm("cvt.rna.tf32.f32 %0, %1;" : "=r"(r) : "f"(v));
    return r;
}
__device__ __forceinline__ void mma8(float* d, const uint32_t* a, const uint32_t* b) {
    asm volatile(
        "mma.sync.aligned.m16n8k8.row.col.f32.tf32.tf32.f32 "
        "{%0,%1,%2,%3}, {%4,%5,%6,%7}, {%8,%9}, {%0,%1,%2,%3};"
        : "+f"(d[0]), "+f"(d[1]), "+f"(d[2]), "+f"(d[3])
        : "r"(a[0]), "r"(a[1]), "r"(a[2]), "r"(a[3]), "r"(b[0]), "r"(b[1]));
}

#define SPAD 36
__device__ __forceinline__ void fill_split(
    float* __restrict__ SH, float* __restrict__ SL,
    const float* __restrict__ p, int ld, int tid)
{
    const int frow = tid >> 1;
    const int fk = (tid & 1) << 4;
    const float* pp = p + (size_t)frow * ld + fk;
    const int so = frow * SPAD + fk;
#pragma unroll
    for (int q = 0; q < 16; q += 4) {
        float4 v = *(const float4*)(pp + q);
        float4 vh, vl;
#pragma unroll
        for (int c = 0; c < 4; c++) {
            const float x = ((const float*)&v)[c];
            const float h = __uint_as_float(f2tf32(x));
            ((float*)&vh)[c] = h;
            ((float*)&vl)[c] = __uint_as_float(f2tf32(x - h));
        }
        *(float4*)(SH + so + q) = vh;
        *(float4*)(SL + so + q) = vl;
    }
}

// ---------------------------------------------------------------------------
// input prep
// ---------------------------------------------------------------------------
__global__ void k_prep_W(const float* __restrict__ Wha, const float* __restrict__ Wda,
                         const float* __restrict__ Whl, const float* __restrict__ Wdl,
                         const float* __restrict__ bha, const float* __restrict__ bda,
                         const float* __restrict__ bhl, const float* __restrict__ bdl)
{
    const int idx = blockIdx.x * 256 + threadIdx.x;
    if (idx < NP * D_) {
        const int n = idx / D_, k = idx - n * D_;
        float v;
        if (n < 512)       v = Wha[k * 512 + n];
        else if (n < 1024) v = Wda[k * 512 + (n - 512)];
        else if (n < 1152) v = Whl[k * 128 + (n - 1024)];
        else               v = Wdl[k * 128 + (n - 1152)];
        g_Wt[idx] = v;
    }
    if (idx < NP) {
        float v;
        if (idx < 512)       v = bha[idx];
        else if (idx < 1024) v = bda[idx - 512];
        else if (idx < 1152) v = bhl[idx - 1024];
        else                 v = bdl[idx - 1152];
        g_bp[idx] = v;
    }
}
__global__ void k_prep_Ua(const float* __restrict__ U) {
    const int idx = blockIdx.x * 256 + threadIdx.x;
    if (idx < A_ * A_) {
        const int n = idx / A_, k = idx - n * A_;
        g_Uat[idx] = U[k * A_ + n];
    }
}
__global__ void k_prep_Ul(const float* __restrict__ U) {
    const int idx = blockIdx.x * 256 + threadIdx.x;
    if (idx < L_ * R_ * R_) {
        const int l = idx / (R_ * R_);
        const int rem = idx - l * (R_ * R_);
        const int s = rem >> 7, r = rem & 127;
        g_Ult[idx] = U[l * R_ * R_ + r * R_ + s];
    }
}

// ---------------------------------------------------------------------------
// Generic tf32x3 warp-MMA GEMM: C[128,128] = A[M,K] @ B[N,K]^T
// zmode 0: zA=zB=z ; 1: zA=z/L, zB=z%L ; 2: zA=z, zB=z/L
// ---------------------------------------------------------------------------
#define SMEMSZ (4 * 128 * SPAD * 4)

__global__ __launch_bounds__(256, 2) void k_mma(
    const float* __restrict__ A, long long sA, int lda,
    const float* __restrict__ B, long long sB, int ldb,
    float* __restrict__ C, long long sC, int ldc,
    const float* __restrict__ bias, int K, int mode, int zmode)
{
    extern __shared__ float sm[];
    float* SAh = sm;
    float* SAl = sm + 128 * SPAD;
    float* SBh = sm + 2 * 128 * SPAD;
    float* SBl = sm + 3 * 128 * SPAD;

    const int tid = threadIdx.x;
    const int lane = tid & 31;
    const int wid = tid >> 5;
    const int wr = wid >> 2;
    const int wc = wid & 3;
    const int g = lane >> 2, t = lane & 3;

    const int z = blockIdx.z;
    int zA = z, zB = z;
    if (zmode == 1) { zA = z / L_; zB = z - zA * L_; }
    else if (zmode == 2) { zB = z / L_; }
    const int m0 = blockIdx.y * 128, n0 = blockIdx.x * 128;
    A += (size_t)zA * sA + (size_t)m0 * lda;
    B += (size_t)zB * sB + (size_t)n0 * ldb;

    float acc[4][4][4];
#pragma unroll
    for (int i = 0; i < 4; i++)
#pragma unroll
        for (int j = 0; j < 4; j++)
#pragma unroll
            for (int q = 0; q < 4; q++) acc[i][j][q] = 0.f;

    for (int kc = 0; kc < K; kc += 32) {
        fill_split(SAh, SAl, A + kc, lda, tid);
        fill_split(SBh, SBl, B + kc, ldb, tid);
        __syncthreads();
#pragma unroll
        for (int ks = 0; ks < 4; ks++) {
            const int kb = ks * 8;
            uint32_t Ah[4][4], Al[4][4], Bh[4][2], Bl[4][2];
#pragma unroll
            for (int mt = 0; mt < 4; mt++) {
                const int rA = (wr * 64 + mt * 16 + g) * SPAD + kb + t;
                Ah[mt][0] = __float_as_uint(SAh[rA]);
                Ah[mt][1] = __float_as_uint(SAh[rA + 8 * SPAD]);
                Ah[mt][2] = __float_as_uint(SAh[rA + 4]);
                Ah[mt][3] = __float_as_uint(SAh[rA + 8 * SPAD + 4]);
                Al[mt][0] = __float_as_uint(SAl[rA]);
                Al[mt][1] = __float_as_uint(SAl[rA + 8 * SPAD]);
                Al[mt][2] = __float_as_uint(SAl[rA + 4]);
                Al[mt][3] = __float_as_uint(SAl[rA + 8 * SPAD + 4]);
            }
#pragma unroll
            for (int nt = 0; nt < 4; nt++) {
                const int cB = (wc * 32 + nt * 8 + g) * SPAD + kb + t;
                Bh[nt][0] = __float_as_uint(SBh[cB]);
                Bh[nt][1] = __float_as_uint(SBh[cB + 4]);
                Bl[nt][0] = __float_as_uint(SBl[cB]);
                Bl[nt][1] = __float_as_uint(SBl[cB + 4]);
            }
#pragma unroll
            for (int mt = 0; mt < 4; mt++)
#pragma unroll
                for (int nt = 0; nt < 4; nt++) mma8(acc[mt][nt], Ah[mt], Bh[nt]);
#pragma unroll
            for (int mt = 0; mt < 4; mt++)
#pragma unroll
                for (int nt = 0; nt < 4; nt++) mma8(acc[mt][nt], Ah[mt], Bl[nt]);
#pragma unroll
            for (int mt = 0; mt < 4; mt++)
#pragma unroll
                for (int nt = 0; nt < 4; nt++) mma8(acc[mt][nt], Al[mt], Bh[nt]);
        }
        __syncthreads();
    }

    C += (size_t)z * sC;
#pragma unroll
    for (int mt = 0; mt < 4; mt++) {
        const int row = m0 + wr * 64 + mt * 16 + g;
#pragma unroll
        for (int nt = 0; nt < 4; nt++) {
            const int col = n0 + wc * 32 + nt * 8 + 2 * t;
            float v0 = acc[mt][nt][0], v1 = acc[mt][nt][1];
            float v2 = acc[mt][nt][2], v3 = acc[mt][nt][3];
            if (mode == 1) {
                const float b0 = bias[col], b1 = bias[col + 1];
                v0 += b0; v1 += b1; v2 += b0; v3 += b1;
                v0 = (v0 > 0.f) ? v0 : expm1f(v0);
                v1 = (v1 > 0.f) ? v1 : expm1f(v1);
                v2 = (v2 > 0.f) ? v2 : expm1f(v2);
                v3 = (v3 > 0.f) ? v3 : expm1f(v3);
            }
            *(float2*)(C + (size_t)row * ldc + col) = make_float2(v0, v1);
            *(float2*)(C + (size_t)(row + 8) * ldc + col) = make_float2(v2, v3);
        }
    }
}

// ---------------------------------------------------------------------------
// 64x64-tile variant for the arc GEMM
// ---------------------------------------------------------------------------
__global__ __launch_bounds__(128) void k_mma64()
{
    __shared__ float SAh[64 * SPAD], SAl[64 * SPAD], SBh[64 * SPAD], SBl[64 * SPAD];
    const int tid = threadIdx.x;
    const int lane = tid & 31;
    const int wid = tid >> 5;
    const int wr = wid >> 1;
    const int wc = wid & 1;
    const int g = lane >> 2, t = lane & 3;

    const int z = blockIdx.z;
    const int m0 = blockIdx.y * 64, n0 = blockIdx.x * 64;
    const float* A = g_marc + (size_t)z * T_ * A_ + (size_t)m0 * A_;
    const float* B = g_proj + (size_t)z * T_ * NP + (size_t)n0 * NP + OFF_DARC;

    float acc[2][4][4];
#pragma unroll
    for (int i = 0; i < 2; i++)
#pragma unroll
        for (int j = 0; j < 4; j++)
#pragma unroll
            for (int q = 0; q < 4; q++) acc[i][j][q] = 0.f;

    for (int kc = 0; kc < A_; kc += 32) {
        fill_split(SAh, SAl, A + kc, A_, tid);
        fill_split(SBh, SBl, B + kc, NP, tid);
        __syncthreads();
#pragma unroll
        for (int ks = 0; ks < 4; ks++) {
            const int kb = ks * 8;
            uint32_t Ah[2][4], Al[2][4], Bh[4][2], Bl[4][2];
#pragma unroll
            for (int mt = 0; mt < 2; mt++) {
                const int rA = (wr * 32 + mt * 16 + g) * SPAD + kb + t;
                Ah[mt][0] = __float_as_uint(SAh[rA]);
                Ah[mt][1] = __float_as_uint(SAh[rA + 8 * SPAD]);
                Ah[mt][2] = __float_as_uint(SAh[rA + 4]);
                Ah[mt][3] = __float_as_uint(SAh[rA + 8 * SPAD + 4]);
                Al[mt][0] = __float_as_uint(SAl[rA]);
                Al[mt][1] = __float_as_uint(SAl[rA + 8 * SPAD]);
                Al[mt][2] = __float_as_uint(SAl[rA + 4]);
                Al[mt][3] = __float_as_uint(SAl[rA + 8 * SPAD + 4]);
            }
#pragma unroll
            for (int nt = 0; nt < 4; nt++) {
                const int cB = (wc * 32 + nt * 8 + g) * SPAD + kb + t;
                Bh[nt][0] = __float_as_uint(SBh[cB]);
                Bh[nt][1] = __float_as_uint(SBh[cB + 4]);
                Bl[nt][0] = __float_as_uint(SBl[cB]);
                Bl[nt][1] = __float_as_uint(SBl[cB + 4]);
            }
#pragma unroll
            for (int mt = 0; mt < 2; mt++)
#pragma unroll
                for (int nt = 0; nt < 4; nt++) mma8(acc[mt][nt], Ah[mt], Bh[nt]);
#pragma unroll
            for (int mt = 0; mt < 2; mt++)
#pragma unroll
                for (int nt = 0; nt < 4; nt++) mma8(acc[mt][nt], Ah[mt], Bl[nt]);
#pragma unroll
            for (int mt = 0; mt < 2; mt++)
#pragma unroll
                for (int nt = 0; nt < 4; nt++) mma8(acc[mt][nt], Al[mt], Bh[nt]);
        }
        __syncthreads();
    }
    float* C = g_arc + (size_t)z * TT;
#pragma unroll
    for (int mt = 0; mt < 2; mt++) {
        const int row = m0 + wr * 32 + mt * 16 + g;
#pragma unroll
        for (int nt = 0; nt < 4; nt++) {
            const int col = n0 + wc * 32 + nt * 8 + 2 * t;
            *(float2*)(C + (size_t)row * T_ + col) = make_float2(acc[mt][nt][0], acc[mt][nt][1]);
            *(float2*)(C + (size_t)(row + 8) * T_ + col) = make_float2(acc[mt][nt][2], acc[mt][nt][3]);
        }
    }
}

// ---------------------------------------------------------------------------
// softmaxes / energy
// ---------------------------------------------------------------------------
__global__ void k_norm_arc()
{
    const int b = blockIdx.x, j = threadIdx.x;
    const float* base = g_arc + (size_t)b * TT;
    float m = -3.4e38f;
#pragma unroll 8
    for (int i = 0; i < T_; i++) m = fmaxf(m, base[i * T_ + j]);
    float s = 0.f;
#pragma unroll 8
    for (int i = 0; i < T_; i++) s += expf(base[i * T_ + j] - m);
    const float ls = logf(s);
    float* nb = g_narc + (size_t)b * TT;
#pragma unroll 8
    for (int i = 0; i < T_; i++) nb[i * T_ + j] = (base[i * T_ + j] - m) - ls;
}

__global__ void k_energy(float* __restrict__ energy)
{
    const int bi = blockIdx.x, b = bi >> 7, i = bi & 127, j = threadIdx.x;
    const size_t base = (size_t)b * (L_ * TT) + (size_t)i * T_ + j;
    float x[L_];
#pragma unroll
    for (int l = 0; l < L_; l++) x[l] = energy[base + (size_t)l * TT];
    float m = -3.4e38f;
#pragma unroll
    for (int l = 0; l < L_; l++) m = fmaxf(m, x[l]);
    float s = 0.f;
#pragma unroll
    for (int l = 0; l < L_; l++) {
        x[l] = __expf(x[l] - m);
        s += x[l];
    }
    const float na = g_narc[(size_t)b * TT + i * T_ + j];
    const float scale = __expf(na) / s;
    float best = -3.4e38f;
    int arg = 0;
#pragma unroll
    for (int l = 0; l < L_; l++) {
        const float e = scale * x[l];
        energy[base + (size_t)l * TT] = e;
        if (e > best) { best = e; arg = l; }
    }
    g_score[(size_t)b * TT + i * T_ + j] = (i == j) ? 0.f : best;
    g_labelid[(size_t)b * TT + i * T_ + j] = arg;
}

// ---------------------------------------------------------------------------
// Chu-Liu-Edmonds MST — smem working set + parallel cycle detection (r13)
// ---------------------------------------------------------------------------
#define MSTSMEM (TT * 4 + TT + TT)

__global__ __launch_bounds__(128) void k_mst(float* __restrict__ out, int has_tail)
{
    extern __shared__ float mst_sm[];
    float* S = mst_sm;
    unsigned char* OI = (unsigned char*)(mst_sm + TT);
    unsigned char* OO = OI + TT;

    const int b = blockIdx.x, tid = threadIdx.x;
    __shared__ int s_par[NLEN];
    __shared__ int s_jump[NLEN];
    __shared__ unsigned char s_cur[NLEN], s_incyc[NLEN];
    __shared__ int s_cyc[NLEN], s_final[NLEN];
    __shared__ unsigned long long s_repA[NLEN], s_repB[NLEN];
    __shared__ int s_clen, s_has, s_depth, s_min;
    __shared__ float s_cw;

    for (int idx = tid; idx < TT; idx += NLEN) {
        const int i = idx >> 7, j = idx & 127;
        S[idx] = g_score[(size_t)b * TT + idx];
        OI[idx] = (unsigned char)((i == j) ? 0 : i);
        OO[idx] = (unsigned char)((i == j) ? 0 : j);
    }
    s_cur[tid] = 1;
    s_repA[tid] = (tid < 64) ? (1ull << tid) : 0ull;
    s_repB[tid] = (tid >= 64) ? (1ull << (tid - 64)) : 0ull;
    s_final[tid] = -2;
    if (tid == 0) s_depth = 0;
    __syncthreads();

    while (true) {
        if (tid == 0) s_par[0] = -1;
        else {
            int par = 0;
            if (s_cur[tid]) {
                float best = S[tid];
                for (int n2 = 1; n2 < NLEN; n2++)
                    if (n2 != tid && s_cur[n2]) {
                        const float v = S[n2 * NLEN + tid];
                        if (v > best) { best = v; par = n2; }
                    }
            }
            s_par[tid] = par;
        }
        if (tid == 0) s_min = 999;
        __syncthreads();

        {
            const int p = s_par[tid];
            s_jump[tid] = (p < 0) ? 0 : p;
        }
        __syncthreads();
#pragma unroll
        for (int r = 0; r < 7; r++) {
            const int j = s_jump[s_jump[tid]];
            __syncthreads();
            s_jump[tid] = j;
            __syncthreads();
        }
        if (tid > 0 && s_cur[tid] && s_jump[tid] != 0) atomicMin(&s_min, tid);
        __syncthreads();

        if (tid == 0) {
            if (s_min >= 999) {
                s_has = 0;
            } else {
                const int i0 = s_min;
                unsigned long long t0 = 0, t1 = 0;
                if (i0 < 64) t0 |= 1ull << i0; else t1 |= 1ull << (i0 - 64);
                int next = i0;
                while (true) {
                    const int p = s_par[next];
                    const int inc = (p < 64) ? (int)((t0 >> p) & 1ull)
                                             : (int)((t1 >> (p - 64)) & 1ull);
                    if (inc) break;
                    next = p;
                    if (next < 64) t0 |= 1ull << next; else t1 |= 1ull << (next - 64);
                }
                int clen = 0;
                s_cyc[clen++] = next;
                int n2 = s_par[next];
                while (n2 != next) { s_cyc[clen++] = n2; n2 = s_par[n2]; }
                s_clen = clen;
                s_has = 1;
                float cw = 0.f;
                for (int c = 0; c < clen; c++) { const int v = s_cyc[c]; cw += S[s_par[v] * NLEN + v]; }
                s_cw = cw;
            }
        }
        __syncthreads();
        if (!s_has) break;

        const int clen = s_clen;
        const int rep = s_cyc[0];
        const float cw = s_cw;
        s_incyc[tid] = 0;
        __syncthreads();
        if (tid < clen) s_incyc[s_cyc[tid]] = 1;
        __syncthreads();

        if (s_cur[tid] && !s_incyc[tid]) {
            const int node = tid;
            float inw = -3.4e38f, outw = -3.4e38f;
            int ine = -1, oute = -1;
            for (int c = 0; c < clen; c++) {
                const int v = s_cyc[c];
                const float sv = S[v * NLEN + node];
                if (sv > inw) { inw = sv; ine = v; }
                const float so = cw + S[node * NLEN + v] - S[s_par[v] * NLEN + v];
                if (so > outw) { outw = so; oute = v; }
            }
            S[rep * NLEN + node] = inw;
            OI[rep * NLEN + node] = OI[ine * NLEN + node];
            OO[rep * NLEN + node] = OO[ine * NLEN + node];
            S[node * NLEN + rep] = outw;
            OO[node * NLEN + rep] = OO[node * NLEN + oute];
            OI[node * NLEN + rep] = OI[node * NLEN + oute];
        }
        __syncthreads();

        const int d = s_depth;
        g_stk_par[((size_t)b * MAXF + d) * NLEN + tid] = (unsigned char)s_par[tid];
        if (tid < clen) g_stk_cyc[((size_t)b * MAXF + d) * NLEN + tid] = (unsigned char)s_cyc[tid];
        __syncthreads();
        if (tid == 0) {
            g_stk_clen[b * MAXF + d] = clen;
            for (int c = 0; c < clen; c++) {
                const int v = s_cyc[c];
                const unsigned long long a0 = s_repA[v], a1 = s_repB[v];
                const size_t ci = (((size_t)b * MAXF + d) * NLEN + c) * 2;
                g_stk_cons[ci] = a0; g_stk_cons[ci + 1] = a1;
                if (c > 0) { s_cur[v] = 0; s_repA[rep] |= a0; s_repB[rep] |= a1; }
            }
            s_depth = d + 1;
        }
        __syncthreads();
    }

    if (tid == 0) {
        s_final[0] = -1;
        for (int node = 1; node < NLEN; node++) {
            if (!s_cur[node]) continue;
            const int p = s_par[node];
            s_final[OO[p * NLEN + node]] = OI[p * NLEN + node];
        }
        for (int d = s_depth - 1; d >= 0; d--) {
            const int clen = g_stk_clen[b * MAXF + d];
            const unsigned char* par = &g_stk_par[((size_t)b * MAXF + d) * NLEN];
            const unsigned char* cyc = &g_stk_cyc[((size_t)b * MAXF + d) * NLEN];
            unsigned long long f0 = 0, f1 = 0;
            for (int x = 0; x < NLEN; x++)
                if (s_final[x] != -2) { if (x < 64) f0 |= 1ull << x; else f1 |= 1ull << (x - 64); }
            int key = -1;
            for (int c = 0; c < clen; c++) {
                const size_t ci = (((size_t)b * MAXF + d) * NLEN + c) * 2;
                if ((g_stk_cons[ci] & f0) | (g_stk_cons[ci + 1] & f1)) { key = cyc[c]; break; }
            }
            if (key < 0) continue;
            int prev = par[key];
            while (prev != key) {
                const int pp = par[prev];
                s_final[OO[pp * NLEN + prev]] = OI[pp * NLEN + prev];
                prev = pp;
            }
        }
    }
    __syncthreads();

    if (has_tail) {
        float hv = 0.f, tv = 1.f;
        const int fe = s_final[tid];
        if (fe != -2) {
            hv = (float)fe;
            const int row = (fe < 0) ? (NLEN - 1) : fe;
            tv = (float)g_labelid[(size_t)b * TT + row * NLEN + tid];
        }
        out[(size_t)EN_ELEMS + b * NLEN + tid] = hv;
        out[(size_t)EN_ELEMS + B_ * NLEN + b * NLEN + tid] = tv;
    }
}

// ---------------------------------------------------------------------------
// Launch — multi-stream fork/join (graph-capturable)
// ---------------------------------------------------------------------------
extern "C" void kernel_launch(void* const* d_in, const int* in_sizes, int n_in,
                              void* d_out, int out_size)
{
    const float* X    = (const float*)d_in[0];
    const float* Wha  = (const float*)d_in[1];
    const float* bha  = (const float*)d_in[2];
    const float* Wda  = (const float*)d_in[3];
    const float* bda  = (const float*)d_in[4];
    const float* Uarc = (const float*)d_in[5];
    const float* Whl  = (const float*)d_in[6];
    const float* bhl  = (const float*)d_in[7];
    const float* Wdl  = (const float*)d_in[8];
    const float* bdl  = (const float*)d_in[9];
    const float* Ulab = (const float*)d_in[10];
    float* out = (float*)d_out;

    void* p;
    cudaGetSymbolAddress(&p, g_Wt);   float* Wt   = (float*)p;
    cudaGetSymbolAddress(&p, g_bp);   float* bp   = (float*)p;
    cudaGetSymbolAddress(&p, g_Uat);  float* Uat  = (float*)p;
    cudaGetSymbolAddress(&p, g_Ult);  float* Ult  = (float*)p;
    cudaGetSymbolAddress(&p, g_proj); float* proj = (float*)p;
    cudaGetSymbolAddress(&p, g_marc); float* marc = (float*)p;
    cudaGetSymbolAddress(&p, g_hl);   float* hl   = (float*)p;

    static int init_done = 0;
    static cudaStream_t s2;
    static cudaEvent_t ev0, evPrep, evProj, evArc;
    if (!init_done) {
        cudaFuncSetAttribute(k_mma, cudaFuncAttributeMaxDynamicSharedMemorySize, SMEMSZ);
        cudaFuncSetAttribute(k_mst, cudaFuncAttributeMaxDynamicSharedMemorySize, MSTSMEM);
        cudaStreamCreateWithFlags(&s2, cudaStreamNonBlocking);
        cudaEventCreateWithFlags(&ev0, cudaEventDisableTiming);
        cudaEventCreateWithFlags(&evPrep, cudaEventDisableTiming);
        cudaEventCreateWithFlags(&evProj, cudaEventDisableTiming);
        cudaEventCreateWithFlags(&evArc, cudaEventDisableTiming);
        init_done = 1;
    }
    const int has_tail = (out_size >= EN_ELEMS + 2 * B_ * T_);

    cudaEventRecord(ev0, 0);
    cudaStreamWaitEvent(s2, ev0, 0);

    k_prep_Ua<<<(A_ * A_ + 255) / 256, 256, 0, s2>>>(Uarc);
    k_prep_Ul<<<(L_ * R_ * R_ + 255) / 256, 256, 0, s2>>>(Ulab);
    cudaEventRecord(evPrep, s2);

    k_prep_W<<<(NP * D_ + 255) / 256, 256>>>(Wha, Wda, Whl, Wdl, bha, bda, bhl, bdl);
    k_mma<<<dim3(NP / 128, BT / 128, 1), 256, SMEMSZ>>>(
        X, 0, D_, Wt, 0, D_, proj, 0, NP, bp, D_, 1, 0);
    cudaEventRecord(evProj, 0);

    cudaStreamWaitEvent(s2, evProj, 0);
    k_mma<<<dim3(A_ / 128, BT / 128, 1), 256, SMEMSZ, s2>>>(
        proj + OFF_HARC, 0, NP, Uat, 0, A_, marc, 0, A_, (float*)0, A_, 0, 0);
    k_mma64<<<dim3(2, 2, B_), 128, 0, s2>>>();
    k_norm_arc<<<B_, T_, 0, s2>>>();
    cudaEventRecord(evArc, s2);

    // main: unfused label path at full k_mma efficiency
    cudaStreamWaitEvent(0, evPrep, 0);
    // hl[b,l] = hlab[b] @ Ult[l]^T: K=128
    k_mma<<<dim3(1, 1, B_ * L_), 256, SMEMSZ>>>(
        proj + OFF_HLAB, (long long)T_ * NP, NP, Ult, (long long)R_ * R_, R_,
        hl, (long long)TT, T_, (float*)0, R_, 0, 1);
    // labsc[b,l] = hl[b,l] @ dlab[b]^T -> out (in-place energy after)
    k_mma<<<dim3(1, 1, B_ * L_), 256, SMEMSZ>>>(
        hl, (long long)TT, T_, proj + OFF_DLAB, (long long)T_ * NP, NP,
        out, (long long)TT, T_, (float*)0, R_, 0, 2);

    cudaStreamWaitEvent(0, evArc, 0);
    k_energy<<<B_ * T_, T_>>>(out);
    k_mst<<<B_, NLEN, MSTSMEM>>>(out, has_tail);
}

// round 15
// speedup vs baseline: 1.0719x; 1.0719x over previous
#include <cuda_runtime.h>
#include <math.h>
#include <stdint.h>

#define B_   32
#define T_   128
#define D_   768
#define A_   512
#define R_   128
#define L_   50
#define NP   1280
#define BT   (B_ * T_)
#define TT   (T_ * T_)
#define EN_ELEMS (B_ * L_ * TT)
#define NLEN 128
#define MAXF 128
#define OFF_HARC 0
#define OFF_DARC 512
#define OFF_HLAB 1024
#define OFF_DLAB 1152

// ---------------------------------------------------------------------------
// Scratch (device globals; allocation is forbidden)
// ---------------------------------------------------------------------------
__device__ float g_Wt[NP * D_];
__device__ float g_bp[NP];
__device__ float g_Uat[A_ * A_];
__device__ float g_Ult[L_ * R_ * R_];
__device__ float g_proj[BT * NP];
__device__ float g_marc[BT * A_];
__device__ float g_arc[B_ * TT];
__device__ float g_narc[B_ * TT];
__device__ float g_score[B_ * TT];
__device__ int   g_labelid[B_ * TT];

// ---------------------------------------------------------------------------
// helpers
// ---------------------------------------------------------------------------
__device__ __forceinline__ uint32_t f2tf32(float v) {
    uint32_t r;
    asm("cvt.rna.tf32.f32 %0, %1;" : "=r"(r) : "f"(v));
    return r;
}
__device__ __forceinline__ void split1(float x, uint32_t& h, uint32_t& l) {
    h = f2tf32(x);
    l = f2tf32(x - __uint_as_float(h));
}
__device__ __forceinline__ void mma8(float* d, const uint32_t* a, const uint32_t* b) {
    asm volatile(
        "mma.sync.aligned.m16n8k8.row.col.f32.tf32.tf32.f32 "
        "{%0,%1,%2,%3}, {%4,%5,%6,%7}, {%8,%9}, {%0,%1,%2,%3};"
        : "+f"(d[0]), "+f"(d[1]), "+f"(d[2]), "+f"(d[3])
        : "r"(a[0]), "r"(a[1]), "r"(a[2]), "r"(a[3]), "r"(b[0]), "r"(b[1]));
}

#define SPAD 36
__device__ __forceinline__ void fill_split(
    float* __restrict__ SH, float* __restrict__ SL,
    const float* __restrict__ p, int ld, int tid)
{
    const int frow = tid >> 1;
    const int fk = (tid & 1) << 4;
    const float* pp = p + (size_t)frow * ld + fk;
    const int so = frow * SPAD + fk;
#pragma unroll
    for (int q = 0; q < 16; q += 4) {
        float4 v = *(const float4*)(pp + q);
        float4 vh, vl;
#pragma unroll
        for (int c = 0; c < 4; c++) {
            const float x = ((const float*)&v)[c];
            const float h = __uint_as_float(f2tf32(x));
            ((float*)&vh)[c] = h;
            ((float*)&vl)[c] = __uint_as_float(f2tf32(x - h));
        }
        *(float4*)(SH + so + q) = vh;
        *(float4*)(SL + so + q) = vl;
    }
}

// ---------------------------------------------------------------------------
// input prep
// ---------------------------------------------------------------------------
__global__ void k_prep_W(const float* __restrict__ Wha, const float* __restrict__ Wda,
                         const float* __restrict__ Whl, const float* __restrict__ Wdl,
                         const float* __restrict__ bha, const float* __restrict__ bda,
                         const float* __restrict__ bhl, const float* __restrict__ bdl)
{
    const int idx = blockIdx.x * 256 + threadIdx.x;
    if (idx < NP * D_) {
        const int n = idx / D_, k = idx - n * D_;
        float v;
        if (n < 512)       v = Wha[k * 512 + n];
        else if (n < 1024) v = Wda[k * 512 + (n - 512)];
        else if (n < 1152) v = Whl[k * 128 + (n - 1024)];
        else               v = Wdl[k * 128 + (n - 1152)];
        g_Wt[idx] = v;
    }
    if (idx < NP) {
        float v;
        if (idx < 512)       v = bha[idx];
        else if (idx < 1024) v = bda[idx - 512];
        else if (idx < 1152) v = bhl[idx - 1024];
        else                 v = bdl[idx - 1152];
        g_bp[idx] = v;
    }
}
__global__ void k_prep_Ua(const float* __restrict__ U) {
    const int idx = blockIdx.x * 256 + threadIdx.x;
    if (idx < A_ * A_) {
        const int n = idx / A_, k = idx - n * A_;
        g_Uat[idx] = U[k * A_ + n];
    }
}
__global__ void k_prep_Ul(const float* __restrict__ U) {
    const int idx = blockIdx.x * 256 + threadIdx.x;
    if (idx < L_ * R_ * R_) {
        const int l = idx / (R_ * R_);
        const int rem = idx - l * (R_ * R_);
        const int s = rem >> 7, r = rem & 127;
        g_Ult[idx] = U[l * R_ * R_ + r * R_ + s];
    }
}

// ---------------------------------------------------------------------------
// Generic tf32x3 warp-MMA GEMM: C[128,128] = A[M,K] @ B[N,K]^T
// ---------------------------------------------------------------------------
#define SMEMSZ (4 * 128 * SPAD * 4)

__global__ __launch_bounds__(256, 2) void k_mma(
    const float* __restrict__ A, long long sA, int lda,
    const float* __restrict__ B, long long sB, int ldb,
    float* __restrict__ C, long long sC, int ldc,
    const float* __restrict__ bias, int K, int mode)
{
    extern __shared__ float sm[];
    float* SAh = sm;
    float* SAl = sm + 128 * SPAD;
    float* SBh = sm + 2 * 128 * SPAD;
    float* SBl = sm + 3 * 128 * SPAD;

    const int tid = threadIdx.x;
    const int lane = tid & 31;
    const int wid = tid >> 5;
    const int wr = wid >> 2;
    const int wc = wid & 3;
    const int g = lane >> 2, t = lane & 3;

    const int z = blockIdx.z;
    const int m0 = blockIdx.y * 128, n0 = blockIdx.x * 128;
    A += (size_t)z * sA + (size_t)m0 * lda;
    B += (size_t)z * sB + (size_t)n0 * ldb;

    float acc[4][4][4];
#pragma unroll
    for (int i = 0; i < 4; i++)
#pragma unroll
        for (int j = 0; j < 4; j++)
#pragma unroll
            for (int q = 0; q < 4; q++) acc[i][j][q] = 0.f;

    for (int kc = 0; kc < K; kc += 32) {
        fill_split(SAh, SAl, A + kc, lda, tid);
        fill_split(SBh, SBl, B + kc, ldb, tid);
        __syncthreads();
#pragma unroll
        for (int ks = 0; ks < 4; ks++) {
            const int kb = ks * 8;
            uint32_t Ah[4][4], Al[4][4], Bh[4][2], Bl[4][2];
#pragma unroll
            for (int mt = 0; mt < 4; mt++) {
                const int rA = (wr * 64 + mt * 16 + g) * SPAD + kb + t;
                Ah[mt][0] = __float_as_uint(SAh[rA]);
                Ah[mt][1] = __float_as_uint(SAh[rA + 8 * SPAD]);
                Ah[mt][2] = __float_as_uint(SAh[rA + 4]);
                Ah[mt][3] = __float_as_uint(SAh[rA + 8 * SPAD + 4]);
                Al[mt][0] = __float_as_uint(SAl[rA]);
                Al[mt][1] = __float_as_uint(SAl[rA + 8 * SPAD]);
                Al[mt][2] = __float_as_uint(SAl[rA + 4]);
                Al[mt][3] = __float_as_uint(SAl[rA + 8 * SPAD + 4]);
            }
#pragma unroll
            for (int nt = 0; nt < 4; nt++) {
                const int cB = (wc * 32 + nt * 8 + g) * SPAD + kb + t;
                Bh[nt][0] = __float_as_uint(SBh[cB]);
                Bh[nt][1] = __float_as_uint(SBh[cB + 4]);
                Bl[nt][0] = __float_as_uint(SBl[cB]);
                Bl[nt][1] = __float_as_uint(SBl[cB + 4]);
            }
#pragma unroll
            for (int mt = 0; mt < 4; mt++)
#pragma unroll
                for (int nt = 0; nt < 4; nt++) mma8(acc[mt][nt], Ah[mt], Bh[nt]);
#pragma unroll
            for (int mt = 0; mt < 4; mt++)
#pragma unroll
                for (int nt = 0; nt < 4; nt++) mma8(acc[mt][nt], Ah[mt], Bl[nt]);
#pragma unroll
            for (int mt = 0; mt < 4; mt++)
#pragma unroll
                for (int nt = 0; nt < 4; nt++) mma8(acc[mt][nt], Al[mt], Bh[nt]);
        }
        __syncthreads();
    }

    C += (size_t)z * sC;
#pragma unroll
    for (int mt = 0; mt < 4; mt++) {
        const int row = m0 + wr * 64 + mt * 16 + g;
#pragma unroll
        for (int nt = 0; nt < 4; nt++) {
            const int col = n0 + wc * 32 + nt * 8 + 2 * t;
            float v0 = acc[mt][nt][0], v1 = acc[mt][nt][1];
            float v2 = acc[mt][nt][2], v3 = acc[mt][nt][3];
            if (mode == 1) {
                const float b0 = bias[col], b1 = bias[col + 1];
                v0 += b0; v1 += b1; v2 += b0; v3 += b1;
                v0 = (v0 > 0.f) ? v0 : expm1f(v0);
                v1 = (v1 > 0.f) ? v1 : expm1f(v1);
                v2 = (v2 > 0.f) ? v2 : expm1f(v2);
                v3 = (v3 > 0.f) ? v3 : expm1f(v3);
            }
            *(float2*)(C + (size_t)row * ldc + col) = make_float2(v0, v1);
            *(float2*)(C + (size_t)(row + 8) * ldc + col) = make_float2(v2, v3);
        }
    }
}

// ---------------------------------------------------------------------------
// 64x64-tile variant for the arc GEMM
// ---------------------------------------------------------------------------
__global__ __launch_bounds__(128) void k_mma64()
{
    __shared__ float SAh[64 * SPAD], SAl[64 * SPAD], SBh[64 * SPAD], SBl[64 * SPAD];
    const int tid = threadIdx.x;
    const int lane = tid & 31;
    const int wid = tid >> 5;
    const int wr = wid >> 1;
    const int wc = wid & 1;
    const int g = lane >> 2, t = lane & 3;

    const int z = blockIdx.z;
    const int m0 = blockIdx.y * 64, n0 = blockIdx.x * 64;
    const float* A = g_marc + (size_t)z * T_ * A_ + (size_t)m0 * A_;
    const float* B = g_proj + (size_t)z * T_ * NP + (size_t)n0 * NP + OFF_DARC;

    float acc[2][4][4];
#pragma unroll
    for (int i = 0; i < 2; i++)
#pragma unroll
        for (int j = 0; j < 4; j++)
#pragma unroll
            for (int q = 0; q < 4; q++) acc[i][j][q] = 0.f;

    for (int kc = 0; kc < A_; kc += 32) {
        fill_split(SAh, SAl, A + kc, A_, tid);
        fill_split(SBh, SBl, B + kc, NP, tid);
        __syncthreads();
#pragma unroll
        for (int ks = 0; ks < 4; ks++) {
            const int kb = ks * 8;
            uint32_t Ah[2][4], Al[2][4], Bh[4][2], Bl[4][2];
#pragma unroll
            for (int mt = 0; mt < 2; mt++) {
                const int rA = (wr * 32 + mt * 16 + g) * SPAD + kb + t;
                Ah[mt][0] = __float_as_uint(SAh[rA]);
                Ah[mt][1] = __float_as_uint(SAh[rA + 8 * SPAD]);
                Ah[mt][2] = __float_as_uint(SAh[rA + 4]);
                Ah[mt][3] = __float_as_uint(SAh[rA + 8 * SPAD + 4]);
                Al[mt][0] = __float_as_uint(SAl[rA]);
                Al[mt][1] = __float_as_uint(SAl[rA + 8 * SPAD]);
                Al[mt][2] = __float_as_uint(SAl[rA + 4]);
                Al[mt][3] = __float_as_uint(SAl[rA + 8 * SPAD + 4]);
            }
#pragma unroll
            for (int nt = 0; nt < 4; nt++) {
                const int cB = (wc * 32 + nt * 8 + g) * SPAD + kb + t;
                Bh[nt][0] = __float_as_uint(SBh[cB]);
                Bh[nt][1] = __float_as_uint(SBh[cB + 4]);
                Bl[nt][0] = __float_as_uint(SBl[cB]);
                Bl[nt][1] = __float_as_uint(SBl[cB + 4]);
            }
#pragma unroll
            for (int mt = 0; mt < 2; mt++)
#pragma unroll
                for (int nt = 0; nt < 4; nt++) mma8(acc[mt][nt], Ah[mt], Bh[nt]);
#pragma unroll
            for (int mt = 0; mt < 2; mt++)
#pragma unroll
                for (int nt = 0; nt < 4; nt++) mma8(acc[mt][nt], Ah[mt], Bl[nt]);
#pragma unroll
            for (int mt = 0; mt < 2; mt++)
#pragma unroll
                for (int nt = 0; nt < 4; nt++) mma8(acc[mt][nt], Al[mt], Bh[nt]);
        }
        __syncthreads();
    }
    float* C = g_arc + (size_t)z * TT;
#pragma unroll
    for (int mt = 0; mt < 2; mt++) {
        const int row = m0 + wr * 32 + mt * 16 + g;
#pragma unroll
        for (int nt = 0; nt < 4; nt++) {
            const int col = n0 + wc * 32 + nt * 8 + 2 * t;
            *(float2*)(C + (size_t)row * T_ + col) = make_float2(acc[mt][nt][0], acc[mt][nt][1]);
            *(float2*)(C + (size_t)(row + 8) * T_ + col) = make_float2(acc[mt][nt][2], acc[mt][nt][3]);
        }
    }
}

// ---------------------------------------------------------------------------
// Fused label path per (b,l)  (r13 proven)
// ---------------------------------------------------------------------------
#define T1PAD 132
#define LABF (18432 + 2 * 128 * SPAD)
#define LABSMEM (LABF * 4)

__global__ __launch_bounds__(256, 2) void k_lab_fused(float* __restrict__ outbuf)
{
    extern __shared__ float sm[];
    float* SAh = sm;
    float* SAl = sm + 128 * SPAD;
    float* SBh = sm + 2 * 128 * SPAD;
    float* SBl = sm + 3 * 128 * SPAD;
    float* T1  = sm;
    float* SB2h = sm + 18432;
    float* SB2l = sm + 18432 + 128 * SPAD;

    const int tid = threadIdx.x;
    const int lane = tid & 31;
    const int wid = tid >> 5;
    const int wr = wid >> 2;
    const int wc = wid & 3;
    const int g = lane >> 2, t = lane & 3;

    const int z = blockIdx.x;
    const int b = z / L_, l = z - b * L_;
    const float* Ahl = g_proj + (size_t)b * T_ * NP + OFF_HLAB;
    const float* Bu  = g_Ult + (size_t)l * R_ * R_;
    const float* Bd  = g_proj + (size_t)b * T_ * NP + OFF_DLAB;

    float acc[4][4][4];
#pragma unroll
    for (int i = 0; i < 4; i++)
#pragma unroll
        for (int j = 0; j < 4; j++)
#pragma unroll
            for (int q = 0; q < 4; q++) acc[i][j][q] = 0.f;

    for (int kc = 0; kc < R_; kc += 32) {
        fill_split(SAh, SAl, Ahl + kc, NP, tid);
        fill_split(SBh, SBl, Bu + kc, R_, tid);
        __syncthreads();
#pragma unroll
        for (int ks = 0; ks < 4; ks++) {
            const int kb = ks * 8;
            uint32_t Ah[4][4], Al[4][4], Bh[4][2], Bl[4][2];
#pragma unroll
            for (int mt = 0; mt < 4; mt++) {
                const int rA = (wr * 64 + mt * 16 + g) * SPAD + kb + t;
                Ah[mt][0] = __float_as_uint(SAh[rA]);
                Ah[mt][1] = __float_as_uint(SAh[rA + 8 * SPAD]);
                Ah[mt][2] = __float_as_uint(SAh[rA + 4]);
                Ah[mt][3] = __float_as_uint(SAh[rA + 8 * SPAD + 4]);
                Al[mt][0] = __float_as_uint(SAl[rA]);
                Al[mt][1] = __float_as_uint(SAl[rA + 8 * SPAD]);
                Al[mt][2] = __float_as_uint(SAl[rA + 4]);
                Al[mt][3] = __float_as_uint(SAl[rA + 8 * SPAD + 4]);
            }
#pragma unroll
            for (int nt = 0; nt < 4; nt++) {
                const int cB = (wc * 32 + nt * 8 + g) * SPAD + kb + t;
                Bh[nt][0] = __float_as_uint(SBh[cB]);
                Bh[nt][1] = __float_as_uint(SBh[cB + 4]);
                Bl[nt][0] = __float_as_uint(SBl[cB]);
                Bl[nt][1] = __float_as_uint(SBl[cB + 4]);
            }
#pragma unroll
            for (int mt = 0; mt < 4; mt++)
#pragma unroll
                for (int nt = 0; nt < 4; nt++) mma8(acc[mt][nt], Ah[mt], Bh[nt]);
#pragma unroll
            for (int mt = 0; mt < 4; mt++)
#pragma unroll
                for (int nt = 0; nt < 4; nt++) mma8(acc[mt][nt], Ah[mt], Bl[nt]);
#pragma unroll
            for (int mt = 0; mt < 4; mt++)
#pragma unroll
                for (int nt = 0; nt < 4; nt++) mma8(acc[mt][nt], Al[mt], Bh[nt]);
        }
        __syncthreads();
    }

#pragma unroll
    for (int mt = 0; mt < 4; mt++) {
        const int row = wr * 64 + mt * 16 + g;
#pragma unroll
        for (int nt = 0; nt < 4; nt++) {
            const int col = wc * 32 + nt * 8 + 2 * t;
            *(float2*)(T1 + row * T1PAD + col) = make_float2(acc[mt][nt][0], acc[mt][nt][1]);
            *(float2*)(T1 + (row + 8) * T1PAD + col) = make_float2(acc[mt][nt][2], acc[mt][nt][3]);
            acc[mt][nt][0] = 0.f; acc[mt][nt][1] = 0.f;
            acc[mt][nt][2] = 0.f; acc[mt][nt][3] = 0.f;
        }
    }
    __syncthreads();

    for (int c2 = 0; c2 < 4; c2++) {
        fill_split(SB2h, SB2l, Bd + c2 * 32, NP, tid);
        __syncthreads();
#pragma unroll
        for (int ks = 0; ks < 4; ks++) {
            const int kb = ks * 8;
            uint32_t Ah[4][4], Al[4][4], Bh[4][2], Bl[4][2];
#pragma unroll
            for (int mt = 0; mt < 4; mt++) {
                const int rA = (wr * 64 + mt * 16 + g) * T1PAD + c2 * 32 + kb + t;
                split1(T1[rA],                 Ah[mt][0], Al[mt][0]);
                split1(T1[rA + 8 * T1PAD],     Ah[mt][1], Al[mt][1]);
                split1(T1[rA + 4],             Ah[mt][2], Al[mt][2]);
                split1(T1[rA + 8 * T1PAD + 4], Ah[mt][3], Al[mt][3]);
            }
#pragma unroll
            for (int nt = 0; nt < 4; nt++) {
                const int cB = (wc * 32 + nt * 8 + g) * SPAD + kb + t;
                Bh[nt][0] = __float_as_uint(SB2h[cB]);
                Bh[nt][1] = __float_as_uint(SB2h[cB + 4]);
                Bl[nt][0] = __float_as_uint(SB2l[cB]);
                Bl[nt][1] = __float_as_uint(SB2l[cB + 4]);
            }
#pragma unroll
            for (int mt = 0; mt < 4; mt++)
#pragma unroll
                for (int nt = 0; nt < 4; nt++) mma8(acc[mt][nt], Ah[mt], Bh[nt]);
#pragma unroll
            for (int mt = 0; mt < 4; mt++)
#pragma unroll
                for (int nt = 0; nt < 4; nt++) mma8(acc[mt][nt], Ah[mt], Bl[nt]);
#pragma unroll
            for (int mt = 0; mt < 4; mt++)
#pragma unroll
                for (int nt = 0; nt < 4; nt++) mma8(acc[mt][nt], Al[mt], Bh[nt]);
        }
        __syncthreads();
    }

    float* C = outbuf + (size_t)z * TT;
#pragma unroll
    for (int mt = 0; mt < 4; mt++) {
        const int row = wr * 64 + mt * 16 + g;
#pragma unroll
        for (int nt = 0; nt < 4; nt++) {
            const int col = wc * 32 + nt * 8 + 2 * t;
            *(float2*)(C + (size_t)row * T_ + col) = make_float2(acc[mt][nt][0], acc[mt][nt][1]);
            *(float2*)(C + (size_t)(row + 8) * T_ + col) = make_float2(acc[mt][nt][2], acc[mt][nt][3]);
        }
    }
}

// ---------------------------------------------------------------------------
// softmaxes / energy
// ---------------------------------------------------------------------------
__global__ void k_norm_arc()
{
    const int b = blockIdx.x, j = threadIdx.x;
    const float* base = g_arc + (size_t)b * TT;
    float m = -3.4e38f;
#pragma unroll 8
    for (int i = 0; i < T_; i++) m = fmaxf(m, base[i * T_ + j]);
    float s = 0.f;
#pragma unroll 8
    for (int i = 0; i < T_; i++) s += expf(base[i * T_ + j] - m);
    const float ls = logf(s);
    float* nb = g_narc + (size_t)b * TT;
#pragma unroll 8
    for (int i = 0; i < T_; i++) nb[i * T_ + j] = (base[i * T_ + j] - m) - ls;
}

__global__ void k_energy(float* __restrict__ energy)
{
    const int bi = blockIdx.x, b = bi >> 7, i = bi & 127, j = threadIdx.x;
    const size_t base = (size_t)b * (L_ * TT) + (size_t)i * T_ + j;
    float x[L_];
#pragma unroll
    for (int l = 0; l < L_; l++) x[l] = energy[base + (size_t)l * TT];
    float m = -3.4e38f;
#pragma unroll
    for (int l = 0; l < L_; l++) m = fmaxf(m, x[l]);
    float s = 0.f;
#pragma unroll
    for (int l = 0; l < L_; l++) {
        x[l] = __expf(x[l] - m);
        s += x[l];
    }
    const float na = g_narc[(size_t)b * TT + i * T_ + j];
    const float scale = __expf(na) / s;
    float best = -3.4e38f;
    int arg = 0;
#pragma unroll
    for (int l = 0; l < L_; l++) {
        const float e = scale * x[l];
        energy[base + (size_t)l * TT] = e;
        if (e > best) { best = e; arg = l; }
    }
    g_score[(size_t)b * TT + i * T_ + j] = (i == j) ? 0.f : best;
    g_labelid[(size_t)b * TT + i * T_ + j] = arg;
}

// ---------------------------------------------------------------------------
// Chu-Liu-Edmonds MST — smem working set, smem stack, parallel cycle
// detection (double-buffered pointer doubling), incremental unwind mask.
// smem: S 64K + OI 16K + OO 16K + stk_par 16K + stk_cyc 256 + cons 4K +
//       clen 512 + off 512  = ~117.5 KB
// ---------------------------------------------------------------------------
#define MST_STK_PAR_OFF (TT * 4 + TT + TT)
#define MSTSMEM (MST_STK_PAR_OFF + 16384 + 256 + 4096 + 512 + 512)

__global__ __launch_bounds__(128) void k_mst(float* __restrict__ out, int has_tail)
{
    extern __shared__ float mst_sm[];
    float* S = mst_sm;
    unsigned char* OI = (unsigned char*)(mst_sm + TT);
    unsigned char* OO = OI + TT;
    unsigned char* STK_PAR = OO + TT;                       // 16384
    unsigned char* STK_CYC = STK_PAR + 16384;               // 256
    unsigned long long* STK_CONS = (unsigned long long*)(STK_CYC + 256); // 256 pairs
    int* STK_CLEN = (int*)((unsigned char*)STK_CONS + 4096);
    int* STK_OFF  = STK_CLEN + 128;

    const int b = blockIdx.x, tid = threadIdx.x;
    __shared__ int s_par[NLEN];
    __shared__ int s_jmp[2][NLEN];
    __shared__ unsigned char s_cur[NLEN], s_incyc[NLEN];
    __shared__ int s_cyc[NLEN], s_final[NLEN];
    __shared__ unsigned long long s_repA[NLEN], s_repB[NLEN];
    __shared__ int s_clen, s_has, s_depth, s_min, s_coff;
    __shared__ float s_cw;

    for (int idx = tid; idx < TT; idx += NLEN) {
        const int i = idx >> 7, j = idx & 127;
        S[idx] = g_score[(size_t)b * TT + idx];
        OI[idx] = (unsigned char)((i == j) ? 0 : i);
        OO[idx] = (unsigned char)((i == j) ? 0 : j);
    }
    s_cur[tid] = 1;
    s_repA[tid] = (tid < 64) ? (1ull << tid) : 0ull;
    s_repB[tid] = (tid >= 64) ? (1ull << (tid - 64)) : 0ull;
    s_final[tid] = -2;
    if (tid == 0) { s_depth = 0; s_coff = 0; }
    __syncthreads();

    while (true) {
        // --- parents: argmax head for each current node ---
        if (tid == 0) s_par[0] = -1;
        else {
            int par = 0;
            if (s_cur[tid]) {
                float best = S[tid];
                for (int n2 = 1; n2 < NLEN; n2++)
                    if (n2 != tid && s_cur[n2]) {
                        const float v = S[n2 * NLEN + tid];
                        if (v > best) { best = v; par = n2; }
                    }
            }
            s_par[tid] = par;
        }
        if (tid == 0) s_min = 999;
        {
            // init doubling buffer 0 (par[0] = -1 -> 0 absorbing)
        }
        __syncthreads();

        // --- parallel cycle detection: double-buffered pointer doubling ---
        {
            const int p = s_par[tid];
            s_jmp[0][tid] = (p < 0) ? 0 : p;
        }
        __syncthreads();
        int cur = 0;
#pragma unroll
        for (int r = 0; r < 7; r++) {
            s_jmp[1 - cur][tid] = s_jmp[cur][s_jmp[cur][tid]];
            __syncthreads();
            cur = 1 - cur;
        }
        if (tid > 0 && s_cur[tid] && s_jmp[cur][tid] != 0) atomicMin(&s_min, tid);
        __syncthreads();

        if (tid == 0) {
            if (s_min >= 999) {
                s_has = 0;
            } else {
                const int i0 = s_min;
                unsigned long long t0 = 0, t1 = 0;
                if (i0 < 64) t0 |= 1ull << i0; else t1 |= 1ull << (i0 - 64);
                int next = i0;
                while (true) {
                    const int p = s_par[next];
                    const int inc = (p < 64) ? (int)((t0 >> p) & 1ull)
                                             : (int)((t1 >> (p - 64)) & 1ull);
                    if (inc) break;
                    next = p;
                    if (next < 64) t0 |= 1ull << next; else t1 |= 1ull << (next - 64);
                }
                int clen = 0;
                s_cyc[clen++] = next;
                int n2 = s_par[next];
                while (n2 != next) { s_cyc[clen++] = n2; n2 = s_par[n2]; }
                s_clen = clen;
                s_has = 1;
                float cw = 0.f;
                for (int c = 0; c < clen; c++) { const int v = s_cyc[c]; cw += S[s_par[v] * NLEN + v]; }
                s_cw = cw;
            }
        }
        __syncthreads();
        if (!s_has) break;

        const int clen = s_clen;
        const int rep = s_cyc[0];
        const float cw = s_cw;
        s_incyc[tid] = 0;
        __syncthreads();
        if (tid < clen) s_incyc[s_cyc[tid]] = 1;
        __syncthreads();

        if (s_cur[tid] && !s_incyc[tid]) {
            const int node = tid;
            float inw = -3.4e38f, outw = -3.4e38f;
            int ine = -1, oute = -1;
            for (int c = 0; c < clen; c++) {
                const int v = s_cyc[c];
                const float sv = S[v * NLEN + node];
                if (sv > inw) { inw = sv; ine = v; }
                const float so = cw + S[node * NLEN + v] - S[s_par[v] * NLEN + v];
                if (so > outw) { outw = so; oute = v; }
            }
            S[rep * NLEN + node] = inw;
            OI[rep * NLEN + node] = OI[ine * NLEN + node];
            OO[rep * NLEN + node] = OO[ine * NLEN + node];
            S[node * NLEN + rep] = outw;
            OO[node * NLEN + rep] = OO[node * NLEN + oute];
            OI[node * NLEN + rep] = OI[node * NLEN + oute];
        }
        __syncthreads();

        // --- push stack frame (shared memory) ---
        const int d = s_depth;
        const int off = s_coff;
        STK_PAR[d * NLEN + tid] = (unsigned char)s_par[tid];
        if (tid < clen) STK_CYC[off + tid] = (unsigned char)s_cyc[tid];
        __syncthreads();
        if (tid == 0) {
            STK_CLEN[d] = clen;
            STK_OFF[d] = off;
            for (int c = 0; c < clen; c++) {
                const int v = s_cyc[c];
                STK_CONS[(off + c) * 2] = s_repA[v];
                STK_CONS[(off + c) * 2 + 1] = s_repB[v];
                if (c > 0) {
                    s_cur[v] = 0;
                    s_repA[rep] |= s_repA[v];
                    s_repB[rep] |= s_repB[v];
                }
            }
            s_coff = off + clen;
            s_depth = d + 1;
        }
        __syncthreads();
    }

    // --- base case + unwind (thread 0, incremental membership mask) ---
    if (tid == 0) {
        unsigned long long f0 = 0, f1 = 0;
        s_final[0] = -1;
        f0 |= 1ull;
        for (int node = 1; node < NLEN; node++) {
            if (!s_cur[node]) continue;
            const int p = s_par[node];
            const int child = OO[p * NLEN + node];
            s_final[child] = OI[p * NLEN + node];
            if (child < 64) f0 |= 1ull << child; else f1 |= 1ull << (child - 64);
        }
        for (int d = s_depth - 1; d >= 0; d--) {
            const int clen = STK_CLEN[d];
            const int off = STK_OFF[d];
            int key = -1;
            for (int c = 0; c < clen; c++) {
                if ((STK_CONS[(off + c) * 2] & f0) | (STK_CONS[(off + c) * 2 + 1] & f1)) {
                    key = STK_CYC[off + c];
                    break;
                }
            }
            if (key < 0) continue;
            const unsigned char* par = &STK_PAR[d * NLEN];
            int prev = par[key];
            while (prev != key) {
                const int pp = par[prev];
                const int child = OO[pp * NLEN + prev];
                s_final[child] = OI[pp * NLEN + prev];
                if (child < 64) f0 |= 1ull << child; else f1 |= 1ull << (child - 64);
                prev = pp;
            }
        }
    }
    __syncthreads();

    if (has_tail) {
        float hv = 0.f, tv = 1.f;
        const int fe = s_final[tid];
        if (fe != -2) {
            hv = (float)fe;
            const int row = (fe < 0) ? (NLEN - 1) : fe;
            tv = (float)g_labelid[(size_t)b * TT + row * NLEN + tid];
        }
        out[(size_t)EN_ELEMS + b * NLEN + tid] = hv;
        out[(size_t)EN_ELEMS + B_ * NLEN + b * NLEN + tid] = tv;
    }
}

// ---------------------------------------------------------------------------
// Launch — multi-stream fork/join (graph-capturable)
// ---------------------------------------------------------------------------
extern "C" void kernel_launch(void* const* d_in, const int* in_sizes, int n_in,
                              void* d_out, int out_size)
{
    const float* X    = (const float*)d_in[0];
    const float* Wha  = (const float*)d_in[1];
    const float* bha  = (const float*)d_in[2];
    const float* Wda  = (const float*)d_in[3];
    const float* bda  = (const float*)d_in[4];
    const float* Uarc = (const float*)d_in[5];
    const float* Whl  = (const float*)d_in[6];
    const float* bhl  = (const float*)d_in[7];
    const float* Wdl  = (const float*)d_in[8];
    const float* bdl  = (const float*)d_in[9];
    const float* Ulab = (const float*)d_in[10];
    float* out = (float*)d_out;

    void* p;
    cudaGetSymbolAddress(&p, g_Wt);   float* Wt   = (float*)p;
    cudaGetSymbolAddress(&p, g_bp);   float* bp   = (float*)p;
    cudaGetSymbolAddress(&p, g_Uat);  float* Uat  = (float*)p;
    cudaGetSymbolAddress(&p, g_proj); float* proj = (float*)p;
    cudaGetSymbolAddress(&p, g_marc); float* marc = (float*)p;

    static int init_done = 0;
    static cudaStream_t s2;
    static cudaEvent_t ev0, evPrep, evProj, evArc;
    if (!init_done) {
        cudaFuncSetAttribute(k_mma, cudaFuncAttributeMaxDynamicSharedMemorySize, SMEMSZ);
        cudaFuncSetAttribute(k_lab_fused, cudaFuncAttributeMaxDynamicSharedMemorySize, LABSMEM);
        cudaFuncSetAttribute(k_mst, cudaFuncAttributeMaxDynamicSharedMemorySize, MSTSMEM);
        cudaStreamCreateWithFlags(&s2, cudaStreamNonBlocking);
        cudaEventCreateWithFlags(&ev0, cudaEventDisableTiming);
        cudaEventCreateWithFlags(&evPrep, cudaEventDisableTiming);
        cudaEventCreateWithFlags(&evProj, cudaEventDisableTiming);
        cudaEventCreateWithFlags(&evArc, cudaEventDisableTiming);
        init_done = 1;
    }
    const int has_tail = (out_size >= EN_ELEMS + 2 * B_ * T_);

    cudaEventRecord(ev0, 0);
    cudaStreamWaitEvent(s2, ev0, 0);

    k_prep_Ua<<<(A_ * A_ + 255) / 256, 256, 0, s2>>>(Uarc);
    k_prep_Ul<<<(L_ * R_ * R_ + 255) / 256, 256, 0, s2>>>(Ulab);
    cudaEventRecord(evPrep, s2);

    k_prep_W<<<(NP * D_ + 255) / 256, 256>>>(Wha, Wda, Whl, Wdl, bha, bda, bhl, bdl);
    k_mma<<<dim3(NP / 128, BT / 128, 1), 256, SMEMSZ>>>(
        X, 0, D_, Wt, 0, D_, proj, 0, NP, bp, D_, 1);
    cudaEventRecord(evProj, 0);

    cudaStreamWaitEvent(s2, evProj, 0);
    k_mma<<<dim3(A_ / 128, BT / 128, 1), 256, SMEMSZ, s2>>>(
        proj + OFF_HARC, 0, NP, Uat, 0, A_, marc, 0, A_, (float*)0, A_, 0);
    k_mma64<<<dim3(2, 2, B_), 128, 0, s2>>>();
    k_norm_arc<<<B_, T_, 0, s2>>>();
    cudaEventRecord(evArc, s2);

    cudaStreamWaitEvent(0, evPrep, 0);
    k_lab_fused<<<B_ * L_, 256, LABSMEM>>>(out);

    cudaStreamWaitEvent(0, evArc, 0);
    k_energy<<<B_ * T_, T_>>>(out);
    k_mst<<<B_, NLEN, MSTSMEM>>>(out, has_tail);
}

// round 16
// speedup vs baseline: 1.6109x; 1.5029x over previous
#include <cuda_runtime.h>
#include <math.h>
#include <stdint.h>

#define B_   32
#define T_   128
#define D_   768
#define A_   512
#define R_   128
#define L_   50
#define NP   1280
#define BT   (B_ * T_)
#define TT   (T_ * T_)
#define EN_ELEMS (B_ * L_ * TT)
#define NLEN 128
#define MAXF 128
#define OFF_HARC 0
#define OFF_DARC 512
#define OFF_HLAB 1024
#define OFF_DLAB 1152

// ---------------------------------------------------------------------------
// Scratch (device globals; allocation is forbidden)
// ---------------------------------------------------------------------------
__device__ float g_Wt[NP * D_];
__device__ float g_bp[NP];
__device__ float g_Uat[A_ * A_];
__device__ float g_Ult[L_ * R_ * R_];
__device__ float g_proj[BT * NP];
__device__ float g_marc[BT * A_];
__device__ float g_arc[B_ * TT];
__device__ float g_narc[B_ * TT];
__device__ float g_score[B_ * TT];
__device__ int   g_labelid[B_ * TT];

// ---------------------------------------------------------------------------
// helpers
// ---------------------------------------------------------------------------
__device__ __forceinline__ uint32_t f2tf32(float v) {
    uint32_t r;
    asm("cvt.rna.tf32.f32 %0, %1;" : "=r"(r) : "f"(v));
    return r;
}
__device__ __forceinline__ void split1(float x, uint32_t& h, uint32_t& l) {
    h = f2tf32(x);
    l = f2tf32(x - __uint_as_float(h));
}
__device__ __forceinline__ void mma8(float* d, const uint32_t* a, const uint32_t* b) {
    asm volatile(
        "mma.sync.aligned.m16n8k8.row.col.f32.tf32.tf32.f32 "
        "{%0,%1,%2,%3}, {%4,%5,%6,%7}, {%8,%9}, {%0,%1,%2,%3};"
        : "+f"(d[0]), "+f"(d[1]), "+f"(d[2]), "+f"(d[3])
        : "r"(a[0]), "r"(a[1]), "r"(a[2]), "r"(a[3]), "r"(b[0]), "r"(b[1]));
}

#define SPAD 36
__device__ __forceinline__ void fill_split(
    float* __restrict__ SH, float* __restrict__ SL,
    const float* __restrict__ p, int ld, int tid)
{
    const int frow = tid >> 1;
    const int fk = (tid & 1) << 4;
    const float* pp = p + (size_t)frow * ld + fk;
    const int so = frow * SPAD + fk;
#pragma unroll
    for (int q = 0; q < 16; q += 4) {
        float4 v = *(const float4*)(pp + q);
        float4 vh, vl;
#pragma unroll
        for (int c = 0; c < 4; c++) {
            const float x = ((const float*)&v)[c];
            const float h = __uint_as_float(f2tf32(x));
            ((float*)&vh)[c] = h;
            ((float*)&vl)[c] = __uint_as_float(f2tf32(x - h));
        }
        *(float4*)(SH + so + q) = vh;
        *(float4*)(SL + so + q) = vl;
    }
}

// ---------------------------------------------------------------------------
// input prep
// ---------------------------------------------------------------------------
__global__ void k_prep_W(const float* __restrict__ Wha, const float* __restrict__ Wda,
                         const float* __restrict__ Whl, const float* __restrict__ Wdl,
                         const float* __restrict__ bha, const float* __restrict__ bda,
                         const float* __restrict__ bhl, const float* __restrict__ bdl)
{
    const int idx = blockIdx.x * 256 + threadIdx.x;
    if (idx < NP * D_) {
        const int n = idx / D_, k = idx - n * D_;
        float v;
        if (n < 512)       v = Wha[k * 512 + n];
        else if (n < 1024) v = Wda[k * 512 + (n - 512)];
        else if (n < 1152) v = Whl[k * 128 + (n - 1024)];
        else               v = Wdl[k * 128 + (n - 1152)];
        g_Wt[idx] = v;
    }
    if (idx < NP) {
        float v;
        if (idx < 512)       v = bha[idx];
        else if (idx < 1024) v = bda[idx - 512];
        else if (idx < 1152) v = bhl[idx - 1024];
        else                 v = bdl[idx - 1152];
        g_bp[idx] = v;
    }
}
__global__ void k_prep_Ua(const float* __restrict__ U) {
    const int idx = blockIdx.x * 256 + threadIdx.x;
    if (idx < A_ * A_) {
        const int n = idx / A_, k = idx - n * A_;
        g_Uat[idx] = U[k * A_ + n];
    }
}
__global__ void k_prep_Ul(const float* __restrict__ U) {
    const int idx = blockIdx.x * 256 + threadIdx.x;
    if (idx < L_ * R_ * R_) {
        const int l = idx / (R_ * R_);
        const int rem = idx - l * (R_ * R_);
        const int s = rem >> 7, r = rem & 127;
        g_Ult[idx] = U[l * R_ * R_ + r * R_ + s];
    }
}

// ---------------------------------------------------------------------------
// Generic tf32x3 warp-MMA GEMM: C[128,128] = A[M,K] @ B[N,K]^T
// ---------------------------------------------------------------------------
#define SMEMSZ (4 * 128 * SPAD * 4)

__global__ __launch_bounds__(256, 2) void k_mma(
    const float* __restrict__ A, long long sA, int lda,
    const float* __restrict__ B, long long sB, int ldb,
    float* __restrict__ C, long long sC, int ldc,
    const float* __restrict__ bias, int K, int mode)
{
    extern __shared__ float sm[];
    float* SAh = sm;
    float* SAl = sm + 128 * SPAD;
    float* SBh = sm + 2 * 128 * SPAD;
    float* SBl = sm + 3 * 128 * SPAD;

    const int tid = threadIdx.x;
    const int lane = tid & 31;
    const int wid = tid >> 5;
    const int wr = wid >> 2;
    const int wc = wid & 3;
    const int g = lane >> 2, t = lane & 3;

    const int z = blockIdx.z;
    const int m0 = blockIdx.y * 128, n0 = blockIdx.x * 128;
    A += (size_t)z * sA + (size_t)m0 * lda;
    B += (size_t)z * sB + (size_t)n0 * ldb;

    float acc[4][4][4];
#pragma unroll
    for (int i = 0; i < 4; i++)
#pragma unroll
        for (int j = 0; j < 4; j++)
#pragma unroll
            for (int q = 0; q < 4; q++) acc[i][j][q] = 0.f;

    for (int kc = 0; kc < K; kc += 32) {
        fill_split(SAh, SAl, A + kc, lda, tid);
        fill_split(SBh, SBl, B + kc, ldb, tid);
        __syncthreads();
#pragma unroll
        for (int ks = 0; ks < 4; ks++) {
            const int kb = ks * 8;
            uint32_t Ah[4][4], Al[4][4], Bh[4][2], Bl[4][2];
#pragma unroll
            for (int mt = 0; mt < 4; mt++) {
                const int rA = (wr * 64 + mt * 16 + g) * SPAD + kb + t;
                Ah[mt][0] = __float_as_uint(SAh[rA]);
                Ah[mt][1] = __float_as_uint(SAh[rA + 8 * SPAD]);
                Ah[mt][2] = __float_as_uint(SAh[rA + 4]);
                Ah[mt][3] = __float_as_uint(SAh[rA + 8 * SPAD + 4]);
                Al[mt][0] = __float_as_uint(SAl[rA]);
                Al[mt][1] = __float_as_uint(SAl[rA + 8 * SPAD]);
                Al[mt][2] = __float_as_uint(SAl[rA + 4]);
                Al[mt][3] = __float_as_uint(SAl[rA + 8 * SPAD + 4]);
            }
#pragma unroll
            for (int nt = 0; nt < 4; nt++) {
                const int cB = (wc * 32 + nt * 8 + g) * SPAD + kb + t;
                Bh[nt][0] = __float_as_uint(SBh[cB]);
                Bh[nt][1] = __float_as_uint(SBh[cB + 4]);
                Bl[nt][0] = __float_as_uint(SBl[cB]);
                Bl[nt][1] = __float_as_uint(SBl[cB + 4]);
            }
#pragma unroll
            for (int mt = 0; mt < 4; mt++)
#pragma unroll
                for (int nt = 0; nt < 4; nt++) mma8(acc[mt][nt], Ah[mt], Bh[nt]);
#pragma unroll
            for (int mt = 0; mt < 4; mt++)
#pragma unroll
                for (int nt = 0; nt < 4; nt++) mma8(acc[mt][nt], Ah[mt], Bl[nt]);
#pragma unroll
            for (int mt = 0; mt < 4; mt++)
#pragma unroll
                for (int nt = 0; nt < 4; nt++) mma8(acc[mt][nt], Al[mt], Bh[nt]);
        }
        __syncthreads();
    }

    C += (size_t)z * sC;
#pragma unroll
    for (int mt = 0; mt < 4; mt++) {
        const int row = m0 + wr * 64 + mt * 16 + g;
#pragma unroll
        for (int nt = 0; nt < 4; nt++) {
            const int col = n0 + wc * 32 + nt * 8 + 2 * t;
            float v0 = acc[mt][nt][0], v1 = acc[mt][nt][1];
            float v2 = acc[mt][nt][2], v3 = acc[mt][nt][3];
            if (mode == 1) {
                const float b0 = bias[col], b1 = bias[col + 1];
                v0 += b0; v1 += b1; v2 += b0; v3 += b1;
                v0 = (v0 > 0.f) ? v0 : expm1f(v0);
                v1 = (v1 > 0.f) ? v1 : expm1f(v1);
                v2 = (v2 > 0.f) ? v2 : expm1f(v2);
                v3 = (v3 > 0.f) ? v3 : expm1f(v3);
            }
            *(float2*)(C + (size_t)row * ldc + col) = make_float2(v0, v1);
            *(float2*)(C + (size_t)(row + 8) * ldc + col) = make_float2(v2, v3);
        }
    }
}

// ---------------------------------------------------------------------------
// 64x64-tile variant for the arc GEMM
// ---------------------------------------------------------------------------
__global__ __launch_bounds__(128) void k_mma64()
{
    __shared__ float SAh[64 * SPAD], SAl[64 * SPAD], SBh[64 * SPAD], SBl[64 * SPAD];
    const int tid = threadIdx.x;
    const int lane = tid & 31;
    const int wid = tid >> 5;
    const int wr = wid >> 1;
    const int wc = wid & 1;
    const int g = lane >> 2, t = lane & 3;

    const int z = blockIdx.z;
    const int m0 = blockIdx.y * 64, n0 = blockIdx.x * 64;
    const float* A = g_marc + (size_t)z * T_ * A_ + (size_t)m0 * A_;
    const float* B = g_proj + (size_t)z * T_ * NP + (size_t)n0 * NP + OFF_DARC;

    float acc[2][4][4];
#pragma unroll
    for (int i = 0; i < 2; i++)
#pragma unroll
        for (int j = 0; j < 4; j++)
#pragma unroll
            for (int q = 0; q < 4; q++) acc[i][j][q] = 0.f;

    for (int kc = 0; kc < A_; kc += 32) {
        fill_split(SAh, SAl, A + kc, A_, tid);
        fill_split(SBh, SBl, B + kc, NP, tid);
        __syncthreads();
#pragma unroll
        for (int ks = 0; ks < 4; ks++) {
            const int kb = ks * 8;
            uint32_t Ah[2][4], Al[2][4], Bh[4][2], Bl[4][2];
#pragma unroll
            for (int mt = 0; mt < 2; mt++) {
                const int rA = (wr * 32 + mt * 16 + g) * SPAD + kb + t;
                Ah[mt][0] = __float_as_uint(SAh[rA]);
                Ah[mt][1] = __float_as_uint(SAh[rA + 8 * SPAD]);
                Ah[mt][2] = __float_as_uint(SAh[rA + 4]);
                Ah[mt][3] = __float_as_uint(SAh[rA + 8 * SPAD + 4]);
                Al[mt][0] = __float_as_uint(SAl[rA]);
                Al[mt][1] = __float_as_uint(SAl[rA + 8 * SPAD]);
                Al[mt][2] = __float_as_uint(SAl[rA + 4]);
                Al[mt][3] = __float_as_uint(SAl[rA + 8 * SPAD + 4]);
            }
#pragma unroll
            for (int nt = 0; nt < 4; nt++) {
                const int cB = (wc * 32 + nt * 8 + g) * SPAD + kb + t;
                Bh[nt][0] = __float_as_uint(SBh[cB]);
                Bh[nt][1] = __float_as_uint(SBh[cB + 4]);
                Bl[nt][0] = __float_as_uint(SBl[cB]);
                Bl[nt][1] = __float_as_uint(SBl[cB + 4]);
            }
#pragma unroll
            for (int mt = 0; mt < 2; mt++)
#pragma unroll
                for (int nt = 0; nt < 4; nt++) mma8(acc[mt][nt], Ah[mt], Bh[nt]);
#pragma unroll
            for (int mt = 0; mt < 2; mt++)
#pragma unroll
                for (int nt = 0; nt < 4; nt++) mma8(acc[mt][nt], Ah[mt], Bl[nt]);
#pragma unroll
            for (int mt = 0; mt < 2; mt++)
#pragma unroll
                for (int nt = 0; nt < 4; nt++) mma8(acc[mt][nt], Al[mt], Bh[nt]);
        }
        __syncthreads();
    }
    float* C = g_arc + (size_t)z * TT;
#pragma unroll
    for (int mt = 0; mt < 2; mt++) {
        const int row = m0 + wr * 32 + mt * 16 + g;
#pragma unroll
        for (int nt = 0; nt < 4; nt++) {
            const int col = n0 + wc * 32 + nt * 8 + 2 * t;
            *(float2*)(C + (size_t)row * T_ + col) = make_float2(acc[mt][nt][0], acc[mt][nt][1]);
            *(float2*)(C + (size_t)(row + 8) * T_ + col) = make_float2(acc[mt][nt][2], acc[mt][nt][3]);
        }
    }
}

// ---------------------------------------------------------------------------
// Fused label path per (b,l)  (r13 proven)
// ---------------------------------------------------------------------------
#define T1PAD 132
#define LABF (18432 + 2 * 128 * SPAD)
#define LABSMEM (LABF * 4)

__global__ __launch_bounds__(256, 2) void k_lab_fused(float* __restrict__ outbuf)
{
    extern __shared__ float sm[];
    float* SAh = sm;
    float* SAl = sm + 128 * SPAD;
    float* SBh = sm + 2 * 128 * SPAD;
    float* SBl = sm + 3 * 128 * SPAD;
    float* T1  = sm;
    float* SB2h = sm + 18432;
    float* SB2l = sm + 18432 + 128 * SPAD;

    const int tid = threadIdx.x;
    const int lane = tid & 31;
    const int wid = tid >> 5;
    const int wr = wid >> 2;
    const int wc = wid & 3;
    const int g = lane >> 2, t = lane & 3;

    const int z = blockIdx.x;
    const int b = z / L_, l = z - b * L_;
    const float* Ahl = g_proj + (size_t)b * T_ * NP + OFF_HLAB;
    const float* Bu  = g_Ult + (size_t)l * R_ * R_;
    const float* Bd  = g_proj + (size_t)b * T_ * NP + OFF_DLAB;

    float acc[4][4][4];
#pragma unroll
    for (int i = 0; i < 4; i++)
#pragma unroll
        for (int j = 0; j < 4; j++)
#pragma unroll
            for (int q = 0; q < 4; q++) acc[i][j][q] = 0.f;

    for (int kc = 0; kc < R_; kc += 32) {
        fill_split(SAh, SAl, Ahl + kc, NP, tid);
        fill_split(SBh, SBl, Bu + kc, R_, tid);
        __syncthreads();
#pragma unroll
        for (int ks = 0; ks < 4; ks++) {
            const int kb = ks * 8;
            uint32_t Ah[4][4], Al[4][4], Bh[4][2], Bl[4][2];
#pragma unroll
            for (int mt = 0; mt < 4; mt++) {
                const int rA = (wr * 64 + mt * 16 + g) * SPAD + kb + t;
                Ah[mt][0] = __float_as_uint(SAh[rA]);
                Ah[mt][1] = __float_as_uint(SAh[rA + 8 * SPAD]);
                Ah[mt][2] = __float_as_uint(SAh[rA + 4]);
                Ah[mt][3] = __float_as_uint(SAh[rA + 8 * SPAD + 4]);
                Al[mt][0] = __float_as_uint(SAl[rA]);
                Al[mt][1] = __float_as_uint(SAl[rA + 8 * SPAD]);
                Al[mt][2] = __float_as_uint(SAl[rA + 4]);
                Al[mt][3] = __float_as_uint(SAl[rA + 8 * SPAD + 4]);
            }
#pragma unroll
            for (int nt = 0; nt < 4; nt++) {
                const int cB = (wc * 32 + nt * 8 + g) * SPAD + kb + t;
                Bh[nt][0] = __float_as_uint(SBh[cB]);
                Bh[nt][1] = __float_as_uint(SBh[cB + 4]);
                Bl[nt][0] = __float_as_uint(SBl[cB]);
                Bl[nt][1] = __float_as_uint(SBl[cB + 4]);
            }
#pragma unroll
            for (int mt = 0; mt < 4; mt++)
#pragma unroll
                for (int nt = 0; nt < 4; nt++) mma8(acc[mt][nt], Ah[mt], Bh[nt]);
#pragma unroll
            for (int mt = 0; mt < 4; mt++)
#pragma unroll
                for (int nt = 0; nt < 4; nt++) mma8(acc[mt][nt], Ah[mt], Bl[nt]);
#pragma unroll
            for (int mt = 0; mt < 4; mt++)
#pragma unroll
                for (int nt = 0; nt < 4; nt++) mma8(acc[mt][nt], Al[mt], Bh[nt]);
        }
        __syncthreads();
    }

#pragma unroll
    for (int mt = 0; mt < 4; mt++) {
        const int row = wr * 64 + mt * 16 + g;
#pragma unroll
        for (int nt = 0; nt < 4; nt++) {
            const int col = wc * 32 + nt * 8 + 2 * t;
            *(float2*)(T1 + row * T1PAD + col) = make_float2(acc[mt][nt][0], acc[mt][nt][1]);
            *(float2*)(T1 + (row + 8) * T1PAD + col) = make_float2(acc[mt][nt][2], acc[mt][nt][3]);
            acc[mt][nt][0] = 0.f; acc[mt][nt][1] = 0.f;
            acc[mt][nt][2] = 0.f; acc[mt][nt][3] = 0.f;
        }
    }
    __syncthreads();

    for (int c2 = 0; c2 < 4; c2++) {
        fill_split(SB2h, SB2l, Bd + c2 * 32, NP, tid);
        __syncthreads();
#pragma unroll
        for (int ks = 0; ks < 4; ks++) {
            const int kb = ks * 8;
            uint32_t Ah[4][4], Al[4][4], Bh[4][2], Bl[4][2];
#pragma unroll
            for (int mt = 0; mt < 4; mt++) {
                const int rA = (wr * 64 + mt * 16 + g) * T1PAD + c2 * 32 + kb + t;
                split1(T1[rA],                 Ah[mt][0], Al[mt][0]);
                split1(T1[rA + 8 * T1PAD],     Ah[mt][1], Al[mt][1]);
                split1(T1[rA + 4],             Ah[mt][2], Al[mt][2]);
                split1(T1[rA + 8 * T1PAD + 4], Ah[mt][3], Al[mt][3]);
            }
#pragma unroll
            for (int nt = 0; nt < 4; nt++) {
                const int cB = (wc * 32 + nt * 8 + g) * SPAD + kb + t;
                Bh[nt][0] = __float_as_uint(SB2h[cB]);
                Bh[nt][1] = __float_as_uint(SB2h[cB + 4]);
                Bl[nt][0] = __float_as_uint(SB2l[cB]);
                Bl[nt][1] = __float_as_uint(SB2l[cB + 4]);
            }
#pragma unroll
            for (int mt = 0; mt < 4; mt++)
#pragma unroll
                for (int nt = 0; nt < 4; nt++) mma8(acc[mt][nt], Ah[mt], Bh[nt]);
#pragma unroll
            for (int mt = 0; mt < 4; mt++)
#pragma unroll
                for (int nt = 0; nt < 4; nt++) mma8(acc[mt][nt], Ah[mt], Bl[nt]);
#pragma unroll
            for (int mt = 0; mt < 4; mt++)
#pragma unroll
                for (int nt = 0; nt < 4; nt++) mma8(acc[mt][nt], Al[mt], Bh[nt]);
        }
        __syncthreads();
    }

    float* C = outbuf + (size_t)z * TT;
#pragma unroll
    for (int mt = 0; mt < 4; mt++) {
        const int row = wr * 64 + mt * 16 + g;
#pragma unroll
        for (int nt = 0; nt < 4; nt++) {
            const int col = wc * 32 + nt * 8 + 2 * t;
            *(float2*)(C + (size_t)row * T_ + col) = make_float2(acc[mt][nt][0], acc[mt][nt][1]);
            *(float2*)(C + (size_t)(row + 8) * T_ + col) = make_float2(acc[mt][nt][2], acc[mt][nt][3]);
        }
    }
}

// ---------------------------------------------------------------------------
// softmaxes / energy
// ---------------------------------------------------------------------------
__global__ void k_norm_arc()
{
    const int b = blockIdx.x, j = threadIdx.x;
    const float* base = g_arc + (size_t)b * TT;
    float m = -3.4e38f;
#pragma unroll 8
    for (int i = 0; i < T_; i++) m = fmaxf(m, base[i * T_ + j]);
    float s = 0.f;
#pragma unroll 8
    for (int i = 0; i < T_; i++) s += expf(base[i * T_ + j] - m);
    const float ls = logf(s);
    float* nb = g_narc + (size_t)b * TT;
#pragma unroll 8
    for (int i = 0; i < T_; i++) nb[i * T_ + j] = (base[i * T_ + j] - m) - ls;
}

__global__ void k_energy(float* __restrict__ energy)
{
    const int bi = blockIdx.x, b = bi >> 7, i = bi & 127, j = threadIdx.x;
    const size_t base = (size_t)b * (L_ * TT) + (size_t)i * T_ + j;
    float x[L_];
#pragma unroll
    for (int l = 0; l < L_; l++) x[l] = energy[base + (size_t)l * TT];
    float m = -3.4e38f;
#pragma unroll
    for (int l = 0; l < L_; l++) m = fmaxf(m, x[l]);
    float s = 0.f;
#pragma unroll
    for (int l = 0; l < L_; l++) {
        x[l] = __expf(x[l] - m);
        s += x[l];
    }
    const float na = g_narc[(size_t)b * TT + i * T_ + j];
    const float scale = __expf(na) / s;
    float best = -3.4e38f;
    int arg = 0;
#pragma unroll
    for (int l = 0; l < L_; l++) {
        const float e = scale * x[l];
        energy[base + (size_t)l * TT] = e;
        if (e > best) { best = e; arg = l; }
    }
    g_score[(size_t)b * TT + i * T_ + j] = (i == j) ? 0.f : best;
    g_labelid[(size_t)b * TT + i * T_ + j] = arg;
}

// ---------------------------------------------------------------------------
// Chu-Liu-Edmonds MST — smem working set, smem stack, parallel cycle
// detection, EXACT incremental parent argmax (first-max semantics preserved).
// ---------------------------------------------------------------------------
#define MST_STK_PAR_OFF (TT * 4 + TT + TT)
#define MSTSMEM (MST_STK_PAR_OFF + 16384 + 256 + 4096 + 512 + 512)

__global__ __launch_bounds__(128) void k_mst(float* __restrict__ out, int has_tail)
{
    extern __shared__ float mst_sm[];
    float* S = mst_sm;
    unsigned char* OI = (unsigned char*)(mst_sm + TT);
    unsigned char* OO = OI + TT;
    unsigned char* STK_PAR = OO + TT;
    unsigned char* STK_CYC = STK_PAR + 16384;
    unsigned long long* STK_CONS = (unsigned long long*)(STK_CYC + 256);
    int* STK_CLEN = (int*)((unsigned char*)STK_CONS + 4096);
    int* STK_OFF  = STK_CLEN + 128;

    const int b = blockIdx.x, tid = threadIdx.x;
    __shared__ int s_par[NLEN];
    __shared__ float s_best[NLEN];
    __shared__ int s_jmp[2][NLEN];
    __shared__ unsigned char s_cur[NLEN], s_incyc[NLEN];
    __shared__ int s_cyc[NLEN], s_final[NLEN];
    __shared__ unsigned long long s_repA[NLEN], s_repB[NLEN];
    __shared__ int s_clen, s_has, s_depth, s_min, s_coff, s_lastrep;
    __shared__ float s_cw;

    for (int idx = tid; idx < TT; idx += NLEN) {
        const int i = idx >> 7, j = idx & 127;
        S[idx] = g_score[(size_t)b * TT + idx];
        OI[idx] = (unsigned char)((i == j) ? 0 : i);
        OO[idx] = (unsigned char)((i == j) ? 0 : j);
    }
    s_cur[tid] = 1;
    s_incyc[tid] = 0;
    s_repA[tid] = (tid < 64) ? (1ull << tid) : 0ull;
    s_repB[tid] = (tid >= 64) ? (1ull << (tid - 64)) : 0ull;
    s_final[tid] = -2;
    if (tid == 0) { s_depth = 0; s_coff = 0; s_lastrep = -2; }
    __syncthreads();

    while (true) {
        // --- parents: exact incremental argmax ---
        int mypar;
        if (tid == 0) {
            mypar = -1;
            s_par[0] = -1;
        } else {
            int par = 0;
            float best = -3.4e38f;
            if (s_cur[tid]) {
                const int lr = s_lastrep;
                bool rescan = (lr == -2) || (tid == lr);
                if (!rescan) {
                    const int po = s_par[tid];
                    if (s_incyc[po]) rescan = true;
                }
                if (rescan) {
                    // full scan, 4 independent chains (first-max preserved)
                    float b0 = S[tid]; int p0 = 0;
                    float b1 = -3.4e38f, b2 = -3.4e38f, b3 = -3.4e38f;
                    int p1 = -1, p2 = -1, p3 = -1;
#define CHK(nn, bb, pp) { const int n2_ = (nn); \
    if (n2_ != tid && s_cur[n2_]) { const float v_ = S[n2_ * NLEN + tid]; \
        if (v_ > bb) { bb = v_; pp = n2_; } } }
                    for (int q = 1; q < 32; q++) CHK(q, b0, p0);
                    for (int q = 32; q < 64; q++) CHK(q, b1, p1);
                    for (int q = 64; q < 96; q++) CHK(q, b2, p2);
                    for (int q = 96; q < 128; q++) CHK(q, b3, p3);
#undef CHK
                    best = b0; par = p0;
                    if (b1 > best) { best = b1; par = p1; }
                    if (b2 > best) { best = b2; par = p2; }
                    if (b3 > best) { best = b3; par = p3; }
                } else {
                    // base still valid over shrunken set; merge candidate lr
                    best = s_best[tid];
                    par = s_par[tid];
                    const float vr = S[lr * NLEN + tid];
                    if (vr > best || (vr == best && lr < par)) { best = vr; par = lr; }
                }
            }
            s_par[tid] = par;
            s_best[tid] = best;
            mypar = par;
        }
        // doubling buffer init folded in (own index; no cross-thread read)
        s_jmp[0][tid] = (mypar < 0) ? 0 : mypar;
        if (tid == 0) s_min = 999;
        __syncthreads();

        // --- parallel cycle detection: double-buffered pointer doubling ---
        int cur = 0;
#pragma unroll
        for (int r = 0; r < 7; r++) {
            s_jmp[1 - cur][tid] = s_jmp[cur][s_jmp[cur][tid]];
            __syncthreads();
            cur = 1 - cur;
        }
        if (tid > 0 && s_cur[tid] && s_jmp[cur][tid] != 0) atomicMin(&s_min, tid);
        __syncthreads();

        if (tid == 0) {
            if (s_min >= 999) {
                s_has = 0;
            } else {
                const int i0 = s_min;
                unsigned long long t0 = 0, t1 = 0;
                if (i0 < 64) t0 |= 1ull << i0; else t1 |= 1ull << (i0 - 64);
                int next = i0;
                while (true) {
                    const int p = s_par[next];
                    const int inc = (p < 64) ? (int)((t0 >> p) & 1ull)
                                             : (int)((t1 >> (p - 64)) & 1ull);
                    if (inc) break;
                    next = p;
                    if (next < 64) t0 |= 1ull << next; else t1 |= 1ull << (next - 64);
                }
                int clen = 0;
                s_cyc[clen++] = next;
                int n2 = s_par[next];
                while (n2 != next) { s_cyc[clen++] = n2; n2 = s_par[n2]; }
                s_clen = clen;
                s_has = 1;
                float cw = 0.f;
                for (int c = 0; c < clen; c++) { const int v = s_cyc[c]; cw += S[s_par[v] * NLEN + v]; }
                s_cw = cw;
            }
        }
        __syncthreads();
        if (!s_has) break;

        const int clen = s_clen;
        const int rep = s_cyc[0];
        const float cw = s_cw;
        s_incyc[tid] = 0;
        __syncthreads();
        if (tid < clen) s_incyc[s_cyc[tid]] = 1;
        __syncthreads();

        if (s_cur[tid] && !s_incyc[tid]) {
            const int node = tid;
            float inw = -3.4e38f, outw = -3.4e38f;
            int ine = -1, oute = -1;
            for (int c = 0; c < clen; c++) {
                const int v = s_cyc[c];
                const float sv = S[v * NLEN + node];
                if (sv > inw) { inw = sv; ine = v; }
                const float so = cw + S[node * NLEN + v] - S[s_par[v] * NLEN + v];
                if (so > outw) { outw = so; oute = v; }
            }
            S[rep * NLEN + node] = inw;
            OI[rep * NLEN + node] = OI[ine * NLEN + node];
            OO[rep * NLEN + node] = OO[ine * NLEN + node];
            S[node * NLEN + rep] = outw;
            OO[node * NLEN + rep] = OO[node * NLEN + oute];
            OI[node * NLEN + rep] = OI[node * NLEN + oute];
        }
        __syncthreads();

        // --- push stack frame (shared memory) ---
        const int d = s_depth;
        const int off = s_coff;
        STK_PAR[d * NLEN + tid] = (unsigned char)s_par[tid];
        if (tid < clen) STK_CYC[off + tid] = (unsigned char)s_cyc[tid];
        __syncthreads();
        if (tid == 0) {
            STK_CLEN[d] = clen;
            STK_OFF[d] = off;
            for (int c = 0; c < clen; c++) {
                const int v = s_cyc[c];
                STK_CONS[(off + c) * 2] = s_repA[v];
                STK_CONS[(off + c) * 2 + 1] = s_repB[v];
                if (c > 0) {
                    s_cur[v] = 0;
                    s_repA[rep] |= s_repA[v];
                    s_repB[rep] |= s_repB[v];
                }
            }
            s_coff = off + clen;
            s_depth = d + 1;
            s_lastrep = rep;
        }
        __syncthreads();
    }

    // --- base case + unwind (thread 0, incremental membership mask) ---
    if (tid == 0) {
        unsigned long long f0 = 0, f1 = 0;
        s_final[0] = -1;
        f0 |= 1ull;
        for (int node = 1; node < NLEN; node++) {
            if (!s_cur[node]) continue;
            const int p = s_par[node];
            const int child = OO[p * NLEN + node];
            s_final[child] = OI[p * NLEN + node];
            if (child < 64) f0 |= 1ull << child; else f1 |= 1ull << (child - 64);
        }
        for (int d = s_depth - 1; d >= 0; d--) {
            const int clen = STK_CLEN[d];
            const int off = STK_OFF[d];
            int key = -1;
            for (int c = 0; c < clen; c++) {
                if ((STK_CONS[(off + c) * 2] & f0) | (STK_CONS[(off + c) * 2 + 1] & f1)) {
                    key = STK_CYC[off + c];
                    break;
                }
            }
            if (key < 0) continue;
            const unsigned char* par = &STK_PAR[d * NLEN];
            int prev = par[key];
            while (prev != key) {
                const int pp = par[prev];
                const int child = OO[pp * NLEN + prev];
                s_final[child] = OI[pp * NLEN + prev];
                if (child < 64) f0 |= 1ull << child; else f1 |= 1ull << (child - 64);
                prev = pp;
            }
        }
    }
    __syncthreads();

    if (has_tail) {
        float hv = 0.f, tv = 1.f;
        const int fe = s_final[tid];
        if (fe != -2) {
            hv = (float)fe;
            const int row = (fe < 0) ? (NLEN - 1) : fe;
            tv = (float)g_labelid[(size_t)b * TT + row * NLEN + tid];
        }
        out[(size_t)EN_ELEMS + b * NLEN + tid] = hv;
        out[(size_t)EN_ELEMS + B_ * NLEN + b * NLEN + tid] = tv;
    }
}

// ---------------------------------------------------------------------------
// Launch — multi-stream fork/join (graph-capturable)
// ---------------------------------------------------------------------------
extern "C" void kernel_launch(void* const* d_in, const int* in_sizes, int n_in,
                              void* d_out, int out_size)
{
    const float* X    = (const float*)d_in[0];
    const float* Wha  = (const float*)d_in[1];
    const float* bha  = (const float*)d_in[2];
    const float* Wda  = (const float*)d_in[3];
    const float* bda  = (const float*)d_in[4];
    const float* Uarc = (const float*)d_in[5];
    const float* Whl  = (const float*)d_in[6];
    const float* bhl  = (const float*)d_in[7];
    const float* Wdl  = (const float*)d_in[8];
    const float* bdl  = (const float*)d_in[9];
    const float* Ulab = (const float*)d_in[10];
    float* out = (float*)d_out;

    void* p;
    cudaGetSymbolAddress(&p, g_Wt);   float* Wt   = (float*)p;
    cudaGetSymbolAddress(&p, g_bp);   float* bp   = (float*)p;
    cudaGetSymbolAddress(&p, g_Uat);  float* Uat  = (float*)p;
    cudaGetSymbolAddress(&p, g_proj); float* proj = (float*)p;
    cudaGetSymbolAddress(&p, g_marc); float* marc = (float*)p;

    static int init_done = 0;
    static cudaStream_t s2;
    static cudaEvent_t ev0, evPrep, evProj, evArc;
    if (!init_done) {
        cudaFuncSetAttribute(k_mma, cudaFuncAttributeMaxDynamicSharedMemorySize, SMEMSZ);
        cudaFuncSetAttribute(k_lab_fused, cudaFuncAttributeMaxDynamicSharedMemorySize, LABSMEM);
        cudaFuncSetAttribute(k_mst, cudaFuncAttributeMaxDynamicSharedMemorySize, MSTSMEM);
        cudaStreamCreateWithFlags(&s2, cudaStreamNonBlocking);
        cudaEventCreateWithFlags(&ev0, cudaEventDisableTiming);
        cudaEventCreateWithFlags(&evPrep, cudaEventDisableTiming);
        cudaEventCreateWithFlags(&evProj, cudaEventDisableTiming);
        cudaEventCreateWithFlags(&evArc, cudaEventDisableTiming);
        init_done = 1;
    }
    const int has_tail = (out_size >= EN_ELEMS + 2 * B_ * T_);

    cudaEventRecord(ev0, 0);
    cudaStreamWaitEvent(s2, ev0, 0);

    k_prep_Ua<<<(A_ * A_ + 255) / 256, 256, 0, s2>>>(Uarc);
    k_prep_Ul<<<(L_ * R_ * R_ + 255) / 256, 256, 0, s2>>>(Ulab);
    cudaEventRecord(evPrep, s2);

    k_prep_W<<<(NP * D_ + 255) / 256, 256>>>(Wha, Wda, Whl, Wdl, bha, bda, bhl, bdl);
    k_mma<<<dim3(NP / 128, BT / 128, 1), 256, SMEMSZ>>>(
        X, 0, D_, Wt, 0, D_, proj, 0, NP, bp, D_, 1);
    cudaEventRecord(evProj, 0);

    cudaStreamWaitEvent(s2, evProj, 0);
    k_mma<<<dim3(A_ / 128, BT / 128, 1), 256, SMEMSZ, s2>>>(
        proj + OFF_HARC, 0, NP, Uat, 0, A_, marc, 0, A_, (float*)0, A_, 0);
    k_mma64<<<dim3(2, 2, B_), 128, 0, s2>>>();
    k_norm_arc<<<B_, T_, 0, s2>>>();
    cudaEventRecord(evArc, s2);

    cudaStreamWaitEvent(0, evPrep, 0);
    k_lab_fused<<<B_ * L_, 256, LABSMEM>>>(out);

    cudaStreamWaitEvent(0, evArc, 0);
    k_energy<<<B_ * T_, T_>>>(out);
    k_mst<<<B_, NLEN, MSTSMEM>>>(out, has_tail);
}